// round 7
// baseline (speedup 1.0000x reference)
#include <cuda_runtime.h>
#include <stdint.h>
#include <math_constants.h>

// Problem shape (fixed by the dataset)
#define D   512
#define BQ  4096
#define KA  32768

#define H_ELEMS (BQ * D)    //  2,097,152
#define A_ELEMS (KA * D)    // 16,777,216

#define BM  128
#define BN  128
#define BD  16
#define PAD 8

// Scratch (no allocs allowed in kernel_launch)
__device__ float g_inv_a[KA];
__device__ unsigned long long g_best[BQ];

// ---------------------------------------------------------------------------
// Reset per-row best keys (graph replays re-run this every launch)
// ---------------------------------------------------------------------------
__global__ void k_init_best() {
    int i = blockIdx.x * blockDim.x + threadIdx.x;
    if (i < BQ) g_best[i] = 0ull;
}

// ---------------------------------------------------------------------------
// inv_a[k] = 1 / max(||A_k||_2, 1e-8)   (one warp per row, float4 loads)
// ---------------------------------------------------------------------------
__global__ void k_inv_norms(const float* __restrict__ A) {
    int warp = (blockIdx.x * blockDim.x + threadIdx.x) >> 5;
    int lane = threadIdx.x & 31;
    if (warp >= KA) return;
    const float4* row = (const float4*)(A + (size_t)warp * D);
    float s = 0.f;
#pragma unroll
    for (int i = 0; i < 4; i++) {
        float4 v = row[lane + i * 32];
        s += v.x * v.x + v.y * v.y + v.z * v.z + v.w * v.w;
    }
#pragma unroll
    for (int o = 16; o > 0; o >>= 1) s += __shfl_xor_sync(0xffffffffu, s, o);
    if (lane == 0) g_inv_a[warp] = 1.0f / fmaxf(sqrtf(s), 1e-8f);
}

// ---------------------------------------------------------------------------
// Fused fp32 GEMM (scores = H·Aᵀ scaled by inv_a) + argmax-over-K reduction.
// 128x128 tile, BD=16 depth slices, 256 threads, 8x8 accum per thread.
// ---------------------------------------------------------------------------
__device__ __forceinline__ unsigned long long pack_key(float v, int n) {
    unsigned int u = __float_as_uint(v);
    u = (u & 0x80000000u) ? ~u : (u | 0x80000000u);   // monotonic fp32 -> u32
    // secondary key inverted so SMALLER n wins ties under max (jnp argmax = first)
    return ((unsigned long long)u << 32) | (unsigned int)(0xFFFFFFFFu - (unsigned int)n);
}

__global__ __launch_bounds__(256, 2)
void k_gemm_argmax(const float* __restrict__ H, const float* __restrict__ A) {
    __shared__ float As[BD][BM + PAD];   // transposed h tile: As[d][m]
    __shared__ float Bs[BD][BN + PAD];   // transposed A tile: Bs[d][n]

    int tid = threadIdx.x;
    int tx = tid & 15;          // n sub-block
    int ty = tid >> 4;          // m sub-block
    int m0 = blockIdx.y * BM;
    int n0 = blockIdx.x * BN;

    float acc[8][8];
#pragma unroll
    for (int i = 0; i < 8; i++)
#pragma unroll
        for (int j = 0; j < 8; j++) acc[i][j] = 0.f;

    // Loader mapping: 256 threads, each loads 2 float4 from H and 2 from A per tile
    int lr = tid >> 2;                 // 0..63 (row), second row = lr+64
    int lc = tid & 3;                  // float4 column within the 16-wide depth slice
    const float* Hp0 = H + (size_t)(m0 + lr)      * D + lc * 4;
    const float* Hp1 = H + (size_t)(m0 + lr + 64) * D + lc * 4;
    const float* Ap0 = A + (size_t)(n0 + lr)      * D + lc * 4;
    const float* Ap1 = A + (size_t)(n0 + lr + 64) * D + lc * 4;

    for (int d0 = 0; d0 < D; d0 += BD) {
        float4 h0 = *(const float4*)(Hp0 + d0);
        float4 h1 = *(const float4*)(Hp1 + d0);
        float4 a0 = *(const float4*)(Ap0 + d0);
        float4 a1 = *(const float4*)(Ap1 + d0);

        __syncthreads();   // previous iteration's smem reads complete
        As[lc * 4 + 0][lr]      = h0.x;
        As[lc * 4 + 1][lr]      = h0.y;
        As[lc * 4 + 2][lr]      = h0.z;
        As[lc * 4 + 3][lr]      = h0.w;
        As[lc * 4 + 0][lr + 64] = h1.x;
        As[lc * 4 + 1][lr + 64] = h1.y;
        As[lc * 4 + 2][lr + 64] = h1.z;
        As[lc * 4 + 3][lr + 64] = h1.w;
        Bs[lc * 4 + 0][lr]      = a0.x;
        Bs[lc * 4 + 1][lr]      = a0.y;
        Bs[lc * 4 + 2][lr]      = a0.z;
        Bs[lc * 4 + 3][lr]      = a0.w;
        Bs[lc * 4 + 0][lr + 64] = a1.x;
        Bs[lc * 4 + 1][lr + 64] = a1.y;
        Bs[lc * 4 + 2][lr + 64] = a1.z;
        Bs[lc * 4 + 3][lr + 64] = a1.w;
        __syncthreads();

#pragma unroll
        for (int d = 0; d < BD; d++) {
            float af[8], bf[8];
            *(float4*)&af[0] = *(const float4*)&As[d][ty * 8];
            *(float4*)&af[4] = *(const float4*)&As[d][ty * 8 + 4];
            *(float4*)&bf[0] = *(const float4*)&Bs[d][tx * 8];
            *(float4*)&bf[4] = *(const float4*)&Bs[d][tx * 8 + 4];
#pragma unroll
            for (int i = 0; i < 8; i++)
#pragma unroll
                for (int j = 0; j < 8; j++)
                    acc[i][j] = fmaf(af[i], bf[j], acc[i][j]);
        }
    }

    // Epilogue: scale by inv_a[n] (h-norm is a per-row positive scale: skip),
    // local argmax over this thread's 8 n's, shuffle-reduce over the 16 threads
    // sharing the same 8 m rows, then one u64 atomicMax per (group, i).
    float inva[8];
#pragma unroll
    for (int j = 0; j < 8; j++) inva[j] = g_inv_a[n0 + tx * 8 + j];

#pragma unroll
    for (int i = 0; i < 8; i++) {
        float bv = -CUDART_INF_F;
        int bn = n0 + tx * 8;
#pragma unroll
        for (int j = 0; j < 8; j++) {
            float s = acc[i][j] * inva[j];
            int n = n0 + tx * 8 + j;
            if (s > bv) { bv = s; bn = n; }
        }
        unsigned long long key = pack_key(bv, bn);
#pragma unroll
        for (int o = 8; o > 0; o >>= 1) {
            unsigned long long other = __shfl_xor_sync(0xffffffffu, key, o, 16);
            key = key > other ? key : other;
        }
        if (tx == 0) atomicMax(&g_best[m0 + ty * 8 + i], key);
    }
}

// ---------------------------------------------------------------------------
// Decode packed keys to indices.
// HYPOTHESIS UNDER TEST (carried from R5; R6 was an infra failure, no signal):
// harness __output__ dtype is float32. Raw int32 index writes read as fp32
// denormals (≈ 0) → rel_err exactly 1.0, as observed under BOTH input
// orderings. Indices < 2^24 so int->float conversion is exact.
// ---------------------------------------------------------------------------
__global__ void k_final(float* __restrict__ out) {
    int i = blockIdx.x * blockDim.x + threadIdx.x;
    if (i < BQ) {
        unsigned int idx = 0xFFFFFFFFu - (unsigned int)(g_best[i] & 0xFFFFFFFFull);
        out[i] = (float)idx;
    }
}

// ---------------------------------------------------------------------------
extern "C" void kernel_launch(void* const* d_in, const int* in_sizes, int n_in,
                              void* d_out, int out_size) {
    // Bind inputs BY SIZE (h: 2,097,152 elems; A: 16,777,216 elems) so either
    // metadata ordering works.
    const float* H = (const float*)d_in[0];
    const float* A = (const float*)d_in[1];
    if (n_in >= 2 && in_sizes[0] == A_ELEMS) {
        H = (const float*)d_in[1];
        A = (const float*)d_in[0];
    }

    k_init_best<<<(BQ + 255) / 256, 256>>>();
    k_inv_norms<<<(KA * 32 + 255) / 256, 256>>>(A);

    dim3 grid(KA / BN, BQ / BM);   // 256 x 32
    k_gemm_argmax<<<grid, 256>>>(H, A);

    k_final<<<(BQ + 255) / 256, 256>>>((float*)d_out);
}

// round 8
// speedup vs baseline: 5.7664x; 5.7664x over previous
#include <cuda_runtime.h>
#include <cuda_bf16.h>
#include <stdint.h>
#include <math_constants.h>

// Problem shape (fixed)
#define D   512
#define BQ  4096
#define KA  32768
#define H_ELEMS (BQ * D)
#define A_ELEMS (KA * D)

// GEMM tiling
#define BM 128
#define BN 128
#define BK 32
#define SSTRIDE 40                       // halves per smem row (32 + 8 pad)
#define STAGE_HALVES (BM * SSTRIDE)      // 5120
#define STAGE_BYTES  (STAGE_HALVES * 2)  // 10240
#define NKT (D / BK)                     // 16 k-tiles
#define WTILES (KA / 32)                 // 1024 warp-tiles of 32 cols per row
#define MARGIN 0.15f                     // >> 2 * 8-sigma bf16 score error

// Device scratch (no allocs allowed)
__device__ __nv_bfloat16 g_Hb[H_ELEMS];                 // bf16 copy of H
__device__ __nv_bfloat16 g_Ab[A_ELEMS];                 // bf16 copy of A, scaled by 1/||a||
__device__ float g_inv_a[KA];
__device__ uint2 g_cand[(size_t)BQ * WTILES * 2];       // top-2 per (row, 32-col tile)

// ---------------------------------------------------------------------------
// H fp32 -> bf16 (no scaling; per-row positive scale is argmax-invariant)
// ---------------------------------------------------------------------------
__global__ void k_prep_h(const float* __restrict__ H) {
    int i = blockIdx.x * blockDim.x + threadIdx.x;      // over H_ELEMS/2
    float2 v = ((const float2*)H)[i];
    __nv_bfloat162 p = __floats2bfloat162_rn(v.x, v.y);
    ((unsigned*)g_Hb)[i] = *(unsigned*)&p;
}

// ---------------------------------------------------------------------------
// Per A-row: inv-norm, then bf16 copy scaled by inv-norm. One warp per row.
// ---------------------------------------------------------------------------
__global__ void k_prep_a(const float* __restrict__ A) {
    int gw = (blockIdx.x * blockDim.x + threadIdx.x) >> 5;
    int lane = threadIdx.x & 31;
    if (gw >= KA) return;
    const float4* row = (const float4*)(A + (size_t)gw * D);
    float4 v[4]; float s = 0.f;
#pragma unroll
    for (int i = 0; i < 4; i++) {
        v[i] = row[lane + 32 * i];
        s += v[i].x * v[i].x + v[i].y * v[i].y + v[i].z * v[i].z + v[i].w * v[i].w;
    }
#pragma unroll
    for (int o = 16; o; o >>= 1) s += __shfl_xor_sync(0xffffffffu, s, o);
    float inv = 1.0f / fmaxf(sqrtf(s), 1e-8f);
    if (lane == 0) g_inv_a[gw] = inv;
    unsigned* dst = (unsigned*)(g_Ab + (size_t)gw * D);
#pragma unroll
    for (int i = 0; i < 4; i++) {
        __nv_bfloat162 p0 = __floats2bfloat162_rn(v[i].x * inv, v[i].y * inv);
        __nv_bfloat162 p1 = __floats2bfloat162_rn(v[i].z * inv, v[i].w * inv);
        int e = lane + 32 * i;
        dst[2 * e]     = *(unsigned*)&p0;
        dst[2 * e + 1] = *(unsigned*)&p1;
    }
}

// ---------------------------------------------------------------------------
// bf16 tensor-core GEMM (scores) + per-(row,32col) top-2 candidate emission.
// 128x128 CTA tile, warps 2(m) x 4(n), warp tile 64x32, mma.m16n8k16.
// ---------------------------------------------------------------------------
#define MMA16816(d, a, b) asm volatile( \
    "mma.sync.aligned.m16n8k16.row.col.f32.bf16.bf16.f32 " \
    "{%0,%1,%2,%3}, {%4,%5,%6,%7}, {%8,%9}, {%0,%1,%2,%3};" \
    : "+f"(d[0]), "+f"(d[1]), "+f"(d[2]), "+f"(d[3]) \
    : "r"(a[0]), "r"(a[1]), "r"(a[2]), "r"(a[3]), "r"(b[0]), "r"(b[1]))

__global__ __launch_bounds__(256, 2) void k_gemm_bf16() {
    __shared__ __nv_bfloat16 sH[2 * STAGE_HALVES];
    __shared__ __nv_bfloat16 sA[2 * STAGE_HALVES];

    int t = threadIdx.x;
    int m0 = blockIdx.y * BM, n0 = blockIdx.x * BN;
    int lane = t & 31, warp = t >> 5;
    int wm = warp >> 2, wn = warp & 3;        // 2 x 4 warp grid
    int lrow = lane >> 2, lcol = lane & 3;

    unsigned sHb = (unsigned)__cvta_generic_to_shared(sH);
    unsigned sAb = (unsigned)__cvta_generic_to_shared(sA);

    // Loader: each thread cp.asyncs 2x16B from H-tile and 2x16B from A-tile
    int lr = t >> 2, lu = t & 3;
    const __nv_bfloat16* gh0 = g_Hb + (size_t)(m0 + lr) * D + lu * 8;
    const __nv_bfloat16* gh1 = g_Hb + (size_t)(m0 + lr + 64) * D + lu * 8;
    const __nv_bfloat16* ga0 = g_Ab + (size_t)(n0 + lr) * D + lu * 8;
    const __nv_bfloat16* ga1 = g_Ab + (size_t)(n0 + lr + 64) * D + lu * 8;
    unsigned sd0 = (unsigned)(lr * SSTRIDE + lu * 8) * 2;
    unsigned sd1 = (unsigned)((lr + 64) * SSTRIDE + lu * 8) * 2;

    // ldmatrix per-lane byte offsets within a stage
    unsigned offA = (unsigned)((wm * 64 + (lane & 15)) * SSTRIDE + ((lane >> 4) * 8)) * 2;
    unsigned offB = (unsigned)((wn * 32 + (lane & 7)) * SSTRIDE + (((lane >> 3) & 1) * 8)) * 2;

    float acc[4][4][4];
#pragma unroll
    for (int mi = 0; mi < 4; mi++)
#pragma unroll
        for (int ni = 0; ni < 4; ni++)
#pragma unroll
            for (int c = 0; c < 4; c++) acc[mi][ni][c] = 0.f;

    auto issue = [&](int kt, int st) {
        unsigned hb = sHb + st * STAGE_BYTES;
        unsigned ab = sAb + st * STAGE_BYTES;
        const __nv_bfloat16* h0 = gh0 + kt * BK;
        const __nv_bfloat16* h1 = gh1 + kt * BK;
        const __nv_bfloat16* a0 = ga0 + kt * BK;
        const __nv_bfloat16* a1 = ga1 + kt * BK;
        asm volatile("cp.async.cg.shared.global [%0], [%1], 16;" :: "r"(hb + sd0), "l"(h0) : "memory");
        asm volatile("cp.async.cg.shared.global [%0], [%1], 16;" :: "r"(hb + sd1), "l"(h1) : "memory");
        asm volatile("cp.async.cg.shared.global [%0], [%1], 16;" :: "r"(ab + sd0), "l"(a0) : "memory");
        asm volatile("cp.async.cg.shared.global [%0], [%1], 16;" :: "r"(ab + sd1), "l"(a1) : "memory");
    };

    issue(0, 0);
    asm volatile("cp.async.commit_group;" ::: "memory");

    for (int kt = 0; kt < NKT; kt++) {
        asm volatile("cp.async.wait_group 0;" ::: "memory");
        __syncthreads();
        if (kt + 1 < NKT) issue(kt + 1, (kt + 1) & 1);
        asm volatile("cp.async.commit_group;" ::: "memory");

        unsigned hb = sHb + (kt & 1) * STAGE_BYTES;
        unsigned ab = sAb + (kt & 1) * STAGE_BYTES;
#pragma unroll
        for (int kf = 0; kf < 2; kf++) {
            unsigned a[4][4], b[4][2];
#pragma unroll
            for (int mi = 0; mi < 4; mi++) {
                unsigned ad = hb + offA + (unsigned)(mi * 16 * SSTRIDE) * 2 + kf * 32;
                asm volatile("ldmatrix.sync.aligned.m8n8.x4.shared.b16 {%0,%1,%2,%3}, [%4];"
                             : "=r"(a[mi][0]), "=r"(a[mi][1]), "=r"(a[mi][2]), "=r"(a[mi][3])
                             : "r"(ad));
            }
#pragma unroll
            for (int ni = 0; ni < 4; ni++) {
                unsigned bd = ab + offB + (unsigned)(ni * 8 * SSTRIDE) * 2 + kf * 32;
                asm volatile("ldmatrix.sync.aligned.m8n8.x2.shared.b16 {%0,%1}, [%2];"
                             : "=r"(b[ni][0]), "=r"(b[ni][1])
                             : "r"(bd));
            }
#pragma unroll
            for (int mi = 0; mi < 4; mi++)
#pragma unroll
                for (int ni = 0; ni < 4; ni++)
                    MMA16816(acc[mi][ni], a[mi], b[ni]);
        }
    }

    // Epilogue: per row (this warp's 32 cols), find top-2 and store.
#pragma unroll
    for (int mi = 0; mi < 4; mi++)
#pragma unroll
        for (int h = 0; h < 2; h++) {
            float s1 = -CUDART_INF_F, s2 = -CUDART_INF_F;
            unsigned i1 = 0, i2 = 0;
#pragma unroll
            for (int ni = 0; ni < 4; ni++)
#pragma unroll
                for (int c = 0; c < 2; c++) {
                    float v = acc[mi][ni][h * 2 + c];
                    unsigned n = (unsigned)(n0 + wn * 32 + ni * 8 + lcol * 2 + c);
                    if (v > s1) { s2 = s1; i2 = i1; s1 = v; i1 = n; }
                    else if (v > s2) { s2 = v; i2 = n; }
                }
            // merge across the 4 lanes sharing this row (xor 1, then xor 2)
#pragma unroll
            for (int off = 1; off <= 2; off <<= 1) {
                float t1 = __shfl_xor_sync(0xffffffffu, s1, off);
                unsigned j1 = __shfl_xor_sync(0xffffffffu, i1, off);
                float t2 = __shfl_xor_sync(0xffffffffu, s2, off);
                unsigned j2 = __shfl_xor_sync(0xffffffffu, i2, off);
                if (t1 > s1) {
                    float os1 = s1; unsigned oi1 = i1;
                    s1 = t1; i1 = j1;
                    if (t2 > os1) { s2 = t2; i2 = j2; } else { s2 = os1; i2 = oi1; }
                } else if (t1 > s2) { s2 = t1; i2 = j1; }
            }
            if (lcol == 0) {
                int rg = m0 + wm * 64 + mi * 16 + lrow + h * 8;
                size_t base = ((size_t)rg * WTILES + (size_t)(blockIdx.x * 4 + wn)) * 2;
                g_cand[base]     = make_uint2(__float_as_uint(s1), i1);
                g_cand[base + 1] = make_uint2(__float_as_uint(s2), i2);
            }
        }
}

// ---------------------------------------------------------------------------
// Per row: approx max over stored candidates, fp32-rescore all within MARGIN,
// exact argmax with first-index tie-break. One warp per row.
// ---------------------------------------------------------------------------
__global__ void k_select(const float* __restrict__ H, const float* __restrict__ A,
                         float* __restrict__ out) {
    int r = (blockIdx.x * blockDim.x + threadIdx.x) >> 5;
    int lane = threadIdx.x & 31;
    if (r >= BQ) return;
    const uint2* cand = g_cand + (size_t)r * WTILES * 2;

    float mx = -CUDART_INF_F;
    for (int j = lane; j < WTILES * 2; j += 32)
        mx = fmaxf(mx, __uint_as_float(cand[j].x));
#pragma unroll
    for (int o = 16; o; o >>= 1) mx = fmaxf(mx, __shfl_xor_sync(0xffffffffu, mx, o));
    float thr = mx - MARGIN;

    const float4* h4 = (const float4*)(H + (size_t)r * D);
    float4 hv[4];
#pragma unroll
    for (int i = 0; i < 4; i++) hv[i] = h4[lane + 32 * i];

    unsigned long long best = 0ull;
    for (int j0 = 0; j0 < WTILES * 2; j0 += 32) {
        uint2 c = cand[j0 + lane];
        unsigned m = __ballot_sync(0xffffffffu, __uint_as_float(c.x) >= thr);
        while (m) {
            int src = __ffs(m) - 1; m &= m - 1;
            unsigned idx = __shfl_sync(0xffffffffu, c.y, src);
            const float4* a4 = (const float4*)(A + (size_t)idx * D);
            float p = 0.f;
#pragma unroll
            for (int i = 0; i < 4; i++) {
                float4 av = a4[lane + 32 * i];
                p += hv[i].x * av.x + hv[i].y * av.y + hv[i].z * av.z + hv[i].w * av.w;
            }
#pragma unroll
            for (int o = 16; o; o >>= 1) p += __shfl_xor_sync(0xffffffffu, p, o);
            float s = p * g_inv_a[idx];
            unsigned u = __float_as_uint(s);
            u = (u & 0x80000000u) ? ~u : (u | 0x80000000u);   // monotonic fp32
            unsigned long long key =
                ((unsigned long long)u << 32) | (unsigned long long)(0xFFFFFFFFu - idx);
            if (key > best) best = key;                        // smaller idx wins ties
        }
    }
    if (lane == 0)
        out[r] = (float)(0xFFFFFFFFu - (unsigned)(best & 0xFFFFFFFFull));
}

// ---------------------------------------------------------------------------
extern "C" void kernel_launch(void* const* d_in, const int* in_sizes, int n_in,
                              void* d_out, int out_size) {
    const float* H = (const float*)d_in[0];
    const float* A = (const float*)d_in[1];
    if (n_in >= 2 && in_sizes[0] == A_ELEMS) {   // bind by size, robust to ordering
        H = (const float*)d_in[1];
        A = (const float*)d_in[0];
    }

    k_prep_h<<<H_ELEMS / 2 / 256, 256>>>(H);       // 4096 blocks
    k_prep_a<<<KA / 8, 256>>>(A);                  // 4096 blocks, warp/row

    dim3 grid(KA / BN, BQ / BM);                   // 256 x 32
    k_gemm_bf16<<<grid, 256>>>();

    k_select<<<BQ / 8, 256>>>(H, A, (float*)d_out); // 512 blocks, warp/row
}